// round 7
// baseline (speedup 1.0000x reference)
#include <cuda_runtime.h>
#include <cuda_fp16.h>

// QConv2d: 3x3 conv, B=16, C=32, N=64, H=W=56, stride 1, pad 1.
// Per-k fp16 (E5M10) requantized accumulation (bit-exact vs reference):
//   p   = fp16(fp32(a * w))  -> FMUL.rn + cvt.rn.f16x2.f32 (packs 2 n-lanes)
//   acc = fp16(acc + p)      -> HADD2
// k order = c*9 + i*3 + j, matching lax.scan order.
//
// R7: weights stored in smem as fp16, packed 16B per (c,i,n-pair) holding all
// three j pairs -> one LDS.128 + 6 exact H2F converts per (c,i). Smem drops to
// 70656B -> 3 CTAs/SM (42 warps). Same 8px/thread shape as R6, c-loop unroll 2.

#define TB 448

#define ROWP 60                            // padded input row (floats)
#define NROWS 6                            // 4 output rows + halo
#define SIN_FLOATS (32 * NROWS * ROWP)     // 11520 -> 46080 B
#define SW_HALVES  (96 * 16 * 8)           // [(c*3+i)][np][8 halves] -> 24576 B
#define SMEM_BYTES (SIN_FLOATS * 4 + SW_HALVES * 2)   // 70656 -> 3 CTAs/SM

__device__ __forceinline__ __half2 cvt_pair(float n0, float n1) {
    unsigned h;
    // cvt.rn.f16x2.f32 d, a, b : a -> upper half, b -> lower half
    asm("cvt.rn.f16x2.f32 %0, %1, %2;" : "=r"(h) : "f"(n1), "f"(n0));
    return *reinterpret_cast<__half2*>(&h);
}

__global__ void __launch_bounds__(TB, 3) qconv2d_kernel(
    const float* __restrict__ x,      // [16][32][56][56]
    const float* __restrict__ w,      // [64][32][3][3] = [64][288]
    const float* __restrict__ bias,   // [64]
    float* __restrict__ out)          // [16][64][56][56]
{
    extern __shared__ float sm[];
    float*  sin = sm;                                  // [c][r(6)][ROWP]
    __half* swh = reinterpret_cast<__half*>(sm + SIN_FLOATS);  // packed weights

    const int yq    = blockIdx.x;     // row quad 0..13 -> rows 4*yq .. 4*yq+3
    const int b     = blockIdx.y;     // batch 0..15
    const int nhalf = blockIdx.z;     // 0: n 0..31, 1: n 32..63
    const int tid   = threadIdx.x;
    const int y0    = 4 * yq;

    // ---- weights: quantize to fp16, pack [(c*3+i)][np][j*2+l] ----
    for (int idx = tid; idx < 32 * 288; idx += TB) {
        int nc = idx / 288;
        int k  = idx % 288;           // consecutive k -> coalesced gmem
        int c  = k / 9;
        int r9 = k % 9;
        int i  = r9 / 3;
        int j  = r9 % 3;
        int np = nc >> 1;
        int l  = nc & 1;
        swh[(((c * 3 + i) * 16) + np) * 8 + j * 2 + l] =
            __float2half_rn(w[(nhalf * 32 + nc) * 288 + k]);
    }

    // ---- input rows y0-1..y0+4, 32 ch, padded rows of 60 (x offset by 1) ----
    const float* xb = x + (size_t)b * 32 * 56 * 56;
    for (int idx = tid; idx < SIN_FLOATS; idx += TB) {
        int c   = idx / (NROWS * ROWP);
        int rr  = idx % (NROWS * ROWP);
        int r   = rr / ROWP;
        int xs  = rr % ROWP;
        int yg  = y0 - 1 + r;
        int xg  = xs - 1;
        float v = 0.0f;
        if (yg >= 0 && yg < 56 && xg >= 0 && xg < 56)
            v = xb[(c * 56 + yg) * 56 + xg];
        sin[idx] = v;
    }
    __syncthreads();

    const int lane = tid & 31;
    const int wrp  = tid >> 5;            // 0..13
    const int np   = lane & 15;           // n-pair within half
    const int h    = lane >> 4;           // px group half 0/1
    const int grp  = wrp * 2 + h;         // 0..27
    const int row  = grp / 7;             // 0..3 (output row within quad)
    const int x0   = (grp % 7) * 8;       // output x base, 8 px per thread

    __half2 acc[8];
    #pragma unroll
    for (int p = 0; p < 8; ++p) acc[p] = __float2half2_rn(0.0f);

    const __half* swt = swh + np * 8;     // +ci*128 halves per (c,i)
    const float*  ab  = sin + row * ROWP + x0;   // 16B aligned

    #pragma unroll 2
    for (int c = 0; c < 32; ++c) {
        #pragma unroll
        for (int i = 0; i < 3; ++i) {
            const float* ar = ab + (c * NROWS + i) * ROWP;
            float4 a03 = *reinterpret_cast<const float4*>(ar);
            float4 a47 = *reinterpret_cast<const float4*>(ar + 4);
            float2 a89 = *reinterpret_cast<const float2*>(ar + 8);
            float av[10] = { a03.x, a03.y, a03.z, a03.w,
                             a47.x, a47.y, a47.z, a47.w,
                             a89.x, a89.y };

            // one LDS.128: all three j weight-pairs (fp16), then exact H2F
            uint4 wb = *reinterpret_cast<const uint4*>(swt + (c * 3 + i) * 128);
            float2 w0 = __half22float2(*reinterpret_cast<__half2*>(&wb.x));
            float2 w1 = __half22float2(*reinterpret_cast<__half2*>(&wb.y));
            float2 w2 = __half22float2(*reinterpret_cast<__half2*>(&wb.z));

            #pragma unroll
            for (int p = 0; p < 8; ++p)
                acc[p] = __hadd2(acc[p], cvt_pair(av[p] * w0.x, av[p] * w0.y));
            #pragma unroll
            for (int p = 0; p < 8; ++p)
                acc[p] = __hadd2(acc[p], cvt_pair(av[p + 1] * w1.x, av[p + 1] * w1.y));
            #pragma unroll
            for (int p = 0; p < 8; ++p)
                acc[p] = __hadd2(acc[p], cvt_pair(av[p + 2] * w2.x, av[p + 2] * w2.y));
        }
    }

    // ---- epilogue: out = fp32(fp16(acc + fp16(bias))) ----
    const int n0 = nhalf * 32 + 2 * np;
    __half2 qb = __halves2half2(__float2half_rn(bias[n0]),
                                __float2half_rn(bias[n0 + 1]));

    float o0v[8], o1v[8];
    #pragma unroll
    for (int p = 0; p < 8; ++p) {
        __half2 r = __hadd2(acc[p], qb);
        o0v[p] = __low2float(r);
        o1v[p] = __high2float(r);
    }

    const int y = y0 + row;
    size_t o0 = (((size_t)b * 64 + n0) * 56 + y) * 56 + x0;
    size_t o1 = (((size_t)b * 64 + n0 + 1) * 56 + y) * 56 + x0;
    #pragma unroll
    for (int q = 0; q < 2; ++q) {
        float4 v0 = make_float4(o0v[q*4+0], o0v[q*4+1], o0v[q*4+2], o0v[q*4+3]);
        float4 v1 = make_float4(o1v[q*4+0], o1v[q*4+1], o1v[q*4+2], o1v[q*4+3]);
        *reinterpret_cast<float4*>(out + o0 + q * 4) = v0;
        *reinterpret_cast<float4*>(out + o1 + q * 4) = v1;
    }
}

extern "C" void kernel_launch(void* const* d_in, const int* in_sizes, int n_in,
                              void* d_out, int out_size)
{
    const float* x    = (const float*)d_in[0];
    const float* w    = (const float*)d_in[1];
    const float* bias = (const float*)d_in[2];
    float* out = (float*)d_out;

    cudaFuncSetAttribute(qconv2d_kernel,
                         cudaFuncAttributeMaxDynamicSharedMemorySize,
                         SMEM_BYTES);

    dim3 grid(14, 16, 2);   // (row quad, batch, n-half)
    qconv2d_kernel<<<grid, TB, SMEM_BYTES>>>(x, w, bias, out);
}

// round 8
// speedup vs baseline: 1.0320x; 1.0320x over previous
#include <cuda_runtime.h>
#include <cuda_fp16.h>

// QConv2d: 3x3 conv, B=16, C=32, N=64, H=W=56, stride 1, pad 1.
// Per-k fp16 (E5M10) requantized accumulation (bit-identical to R6):
//   p   = fp16(fp32(a * w))  -> FMUL.rn + cvt.rn.f16x2.f32 (packs 2 n-lanes)
//   acc = fp16(acc + p)      -> HADD2
// k order = c*9 + i*3 + j, matching lax.scan order.
//
// R8: wave-packing fix. Block = 4 rows x 16 n, TB=224, 8 px/thread (R6 inner).
// Smem 64512B -> 3 CTAs/SM, conc = 444; grid 896 = 2.02 waves (vs R6's 1.51
// waves = 75.7% packing, which matched its measured issue 74.5%).

#define TB 224

#define ROWP 60                            // padded input row (floats)
#define NROWS 6                            // 4 output rows + halo
#define SIN_FLOATS (32 * NROWS * ROWP)     // 11520 -> 46080 B
#define SW_FLOATS  (288 * 16)              // 4608  -> 18432 B
#define SMEM_BYTES ((SIN_FLOATS + SW_FLOATS) * 4)   // 64512 -> 3 CTAs/SM

__device__ __forceinline__ __half2 cvt_pair(float n0, float n1) {
    unsigned h;
    // cvt.rn.f16x2.f32 d, a, b : a -> upper half, b -> lower half
    asm("cvt.rn.f16x2.f32 %0, %1, %2;" : "=r"(h) : "f"(n1), "f"(n0));
    return *reinterpret_cast<__half2*>(&h);
}

__global__ void __launch_bounds__(TB, 3) qconv2d_kernel(
    const float* __restrict__ x,      // [16][32][56][56]
    const float* __restrict__ w,      // [64][32][3][3] = [64][288]
    const float* __restrict__ bias,   // [64]
    float* __restrict__ out)          // [16][64][56][56]
{
    extern __shared__ float sm[];
    float* sin = sm;                      // [c][r(6)][ROWP]
    float* sw  = sm + SIN_FLOATS;         // [k=288][nc=16], fp16-valued fp32

    const int yq  = blockIdx.x;       // row quad 0..13 -> rows 4*yq .. 4*yq+3
    const int b   = blockIdx.y;       // batch 0..15
    const int nq  = blockIdx.z;       // n quarter 0..3 -> n = 16*nq .. 16*nq+15
    const int tid = threadIdx.x;
    const int y0  = 4 * yq;

    // ---- weights for this n-quarter: coalesced read, transpose to [k][nc] ----
    for (int idx = tid; idx < 16 * 288; idx += TB) {
        int nc = idx / 288;
        int k  = idx % 288;
        sw[k * 16 + nc] = __half2float(__float2half_rn(w[(nq * 16 + nc) * 288 + k]));
    }

    // ---- input rows y0-1..y0+4, 32 ch, padded rows of 60 (x offset by 1) ----
    const float* xb = x + (size_t)b * 32 * 56 * 56;
    for (int idx = tid; idx < SIN_FLOATS; idx += TB) {
        int c   = idx / (NROWS * ROWP);
        int rr  = idx % (NROWS * ROWP);
        int r   = rr / ROWP;
        int xs  = rr % ROWP;
        int yg  = y0 - 1 + r;
        int xg  = xs - 1;
        float v = 0.0f;
        if (yg >= 0 && yg < 56 && xg >= 0 && xg < 56)
            v = xb[(c * 56 + yg) * 56 + xg];
        sin[idx] = v;
    }
    __syncthreads();

    const int lane = tid & 31;
    const int wrp  = tid >> 5;            // 0..6
    const int np   = lane & 7;            // n-pair within quarter (0..7)
    const int h    = lane >> 3;           // px group slot 0..3
    const int grp  = wrp * 4 + h;         // 0..27
    const int row  = grp / 7;             // 0..3 (output row within quad)
    const int x0   = (grp % 7) * 8;       // output x base, 8 px per thread

    __half2 acc[8];
    #pragma unroll
    for (int p = 0; p < 8; ++p) acc[p] = __float2half2_rn(0.0f);

    const float* swt = sw + 2 * np;
    const float* ab  = sin + row * ROWP + x0;   // 16B aligned

    #pragma unroll 2
    for (int c = 0; c < 32; ++c) {
        #pragma unroll
        for (int i = 0; i < 3; ++i) {
            const float* ar = ab + (c * NROWS + i) * ROWP;
            float4 a03 = *reinterpret_cast<const float4*>(ar);
            float4 a47 = *reinterpret_cast<const float4*>(ar + 4);
            float2 a89 = *reinterpret_cast<const float2*>(ar + 8);
            float av[10] = { a03.x, a03.y, a03.z, a03.w,
                             a47.x, a47.y, a47.z, a47.w,
                             a89.x, a89.y };

            const float* wr = swt + (c * 9 + i * 3) * 16;
            float2 w0 = *reinterpret_cast<const float2*>(wr);        // j=0
            float2 w1 = *reinterpret_cast<const float2*>(wr + 16);   // j=1
            float2 w2 = *reinterpret_cast<const float2*>(wr + 32);   // j=2

            #pragma unroll
            for (int p = 0; p < 8; ++p)
                acc[p] = __hadd2(acc[p], cvt_pair(av[p] * w0.x, av[p] * w0.y));
            #pragma unroll
            for (int p = 0; p < 8; ++p)
                acc[p] = __hadd2(acc[p], cvt_pair(av[p + 1] * w1.x, av[p + 1] * w1.y));
            #pragma unroll
            for (int p = 0; p < 8; ++p)
                acc[p] = __hadd2(acc[p], cvt_pair(av[p + 2] * w2.x, av[p + 2] * w2.y));
        }
    }

    // ---- epilogue: out = fp32(fp16(acc + fp16(bias))) ----
    const int n0 = nq * 16 + 2 * np;
    __half2 qb = __halves2half2(__float2half_rn(bias[n0]),
                                __float2half_rn(bias[n0 + 1]));

    float o0v[8], o1v[8];
    #pragma unroll
    for (int p = 0; p < 8; ++p) {
        __half2 r = __hadd2(acc[p], qb);
        o0v[p] = __low2float(r);
        o1v[p] = __high2float(r);
    }

    const int y = y0 + row;
    size_t o0 = (((size_t)b * 64 + n0) * 56 + y) * 56 + x0;
    size_t o1 = (((size_t)b * 64 + n0 + 1) * 56 + y) * 56 + x0;
    #pragma unroll
    for (int q = 0; q < 2; ++q) {
        float4 v0 = make_float4(o0v[q*4+0], o0v[q*4+1], o0v[q*4+2], o0v[q*4+3]);
        float4 v1 = make_float4(o1v[q*4+0], o1v[q*4+1], o1v[q*4+2], o1v[q*4+3]);
        *reinterpret_cast<float4*>(out + o0 + q * 4) = v0;
        *reinterpret_cast<float4*>(out + o1 + q * 4) = v1;
    }
}

extern "C" void kernel_launch(void* const* d_in, const int* in_sizes, int n_in,
                              void* d_out, int out_size)
{
    const float* x    = (const float*)d_in[0];
    const float* w    = (const float*)d_in[1];
    const float* bias = (const float*)d_in[2];
    float* out = (float*)d_out;

    cudaFuncSetAttribute(qconv2d_kernel,
                         cudaFuncAttributeMaxDynamicSharedMemorySize,
                         SMEM_BYTES);

    dim3 grid(14, 16, 4);   // (row quad, batch, n quarter)
    qconv2d_kernel<<<grid, TB, SMEM_BYTES>>>(x, w, bias, out);
}